// round 1
// baseline (speedup 1.0000x reference)
#include <cuda_runtime.h>
#include <cuda_bf16.h>
#include <stdint.h>

#define N_NODES 16384
#define FDIM    128
#define NCLS    40

#define BM 128
#define BK 64
#define KTILES (N_NODES / BK)   // 256

// Scratch (static device globals — no allocation allowed)
__device__ float         g_support[(size_t)N_NODES * FDIM];   // 8 MB
__device__ __nv_bfloat16 g_featb [(size_t)N_NODES * FDIM];    // 4 MB

__device__ __forceinline__ uint32_t smaddr(const void* p) {
    return (uint32_t)__cvta_generic_to_shared(p);
}

// ---------------------------------------------------------------------------
// Convert x (fp32) -> g_featb (bf16)
// ---------------------------------------------------------------------------
__global__ void cvt_x_kernel(const float* __restrict__ in) {
    int i = blockIdx.x * blockDim.x + threadIdx.x;
    int stride = gridDim.x * blockDim.x;
    const int n4 = N_NODES * FDIM / 4;
    const float4* in4 = (const float4*)in;
    __nv_bfloat162* ob = (__nv_bfloat162*)g_featb;
    for (; i < n4; i += stride) {
        float4 v = in4[i];
        ob[2 * i]     = __float22bfloat162_rn(make_float2(v.x, v.y));
        ob[2 * i + 1] = __float22bfloat162_rn(make_float2(v.z, v.w));
    }
}

// ---------------------------------------------------------------------------
// SpMM: g_support[N,128] = adj(fp32, converted inline to bf16) @ g_featb[N,128]
// CTA tile: 128(M) x 128(N=all), BK=64, 256 threads, double buffered.
// A path: LDG.128 fp32 -> cvt bf16 -> swizzled STS.  B path: cp.async bf16.
// mma.sync.m16n8k16 bf16, fp32 accum. Warp grid 4(M) x 2(N), 32x64 per warp.
// ---------------------------------------------------------------------------
__global__ void __launch_bounds__(256, 1)
spmm_kernel(const float* __restrict__ A) {
    extern __shared__ char smem[];
    char* As = smem;               // 2 buffers * 128*64*2B = 32768
    char* Bs = smem + 32768;       // 2 buffers * 64*128*2B = 32768
    const uint32_t as0 = smaddr(As);
    const uint32_t bs0 = smaddr(Bs);

    const int t    = threadIdx.x;
    const int lane = t & 31;
    const int warp = t >> 5;
    const int wm = warp >> 1;      // 0..3
    const int wn = warp & 1;       // 0..1
    const int m0 = blockIdx.x * BM;

    const int ar = t >> 4;         // 0..15
    const int af = t & 15;         // float4 slot within 64-float row / 16B chunk id

    float4 areg[8];
    float acc[2][8][4];
    #pragma unroll
    for (int i = 0; i < 2; ++i)
        #pragma unroll
        for (int j = 0; j < 8; ++j)
            #pragma unroll
            for (int k = 0; k < 4; ++k) acc[i][j][k] = 0.f;

    const float* Abase = A + (size_t)m0 * N_NODES;

    auto ldgA = [&](int kt) {
        const float* src = Abase + (size_t)kt * BK;
        #pragma unroll
        for (int p = 0; p < 8; ++p) {
            int r = p * 16 + ar;
            areg[p] = *(const float4*)(src + (size_t)r * N_NODES + af * 4);
        }
    };
    auto stsA = [&](int buf) {
        char* dst = As + buf * 16384;
        const int c = af >> 1, h = af & 1;
        #pragma unroll
        for (int p = 0; p < 8; ++p) {
            int r = p * 16 + ar;
            int off = r * 128 + (((c ^ (r & 7)) << 4) | (h << 3));
            __nv_bfloat162 lo = __float22bfloat162_rn(make_float2(areg[p].x, areg[p].y));
            __nv_bfloat162 hi = __float22bfloat162_rn(make_float2(areg[p].z, areg[p].w));
            uint2 v;
            v.x = *(uint32_t*)&lo;
            v.y = *(uint32_t*)&hi;
            *(uint2*)(dst + off) = v;
        }
    };
    auto cpB = [&](int kt, int buf) {
        const char* gsrc = (const char*)(g_featb + (size_t)kt * BK * FDIM);
        const uint32_t sbase = bs0 + buf * 16384;
        #pragma unroll
        for (int p = 0; p < 4; ++p) {
            int r = p * 16 + ar;
            uint32_t soff = r * 256 + ((af ^ ((r & 7) << 1)) << 4);
            asm volatile("cp.async.cg.shared.global [%0], [%1], 16;\n"
                         :: "r"(sbase + soff), "l"(gsrc + (size_t)r * 256 + af * 16));
        }
    };
    auto compute = [&](int buf) {
        const uint32_t ab = as0 + buf * 16384;
        const uint32_t bb = bs0 + buf * 16384;
        #pragma unroll
        for (int ks = 0; ks < 4; ++ks) {
            uint32_t a[2][4];
            #pragma unroll
            for (int mt = 0; mt < 2; ++mt) {
                int r = wm * 32 + mt * 16 + (lane & 15);
                int c = ks * 2 + (lane >> 4);
                uint32_t addr = ab + r * 128 + ((c ^ (r & 7)) << 4);
                asm volatile("ldmatrix.sync.aligned.m8n8.x4.shared.b16 {%0,%1,%2,%3}, [%4];\n"
                    : "=r"(a[mt][0]), "=r"(a[mt][1]), "=r"(a[mt][2]), "=r"(a[mt][3])
                    : "r"(addr));
            }
            uint32_t b[8][2];
            #pragma unroll
            for (int nt = 0; nt < 8; ++nt) {
                int r = ks * 16 + (lane & 15);
                int c = wn * 8 + nt;
                uint32_t addr = bb + r * 256 + ((c ^ ((r & 7) << 1)) << 4);
                asm volatile("ldmatrix.sync.aligned.m8n8.x2.trans.shared.b16 {%0,%1}, [%2];\n"
                    : "=r"(b[nt][0]), "=r"(b[nt][1]) : "r"(addr));
            }
            #pragma unroll
            for (int mt = 0; mt < 2; ++mt)
                #pragma unroll
                for (int nt = 0; nt < 8; ++nt) {
                    asm volatile(
                        "mma.sync.aligned.m16n8k16.row.col.f32.bf16.bf16.f32 "
                        "{%0,%1,%2,%3}, {%4,%5,%6,%7}, {%8,%9}, {%0,%1,%2,%3};\n"
                        : "+f"(acc[mt][nt][0]), "+f"(acc[mt][nt][1]),
                          "+f"(acc[mt][nt][2]), "+f"(acc[mt][nt][3])
                        : "r"(a[mt][0]), "r"(a[mt][1]), "r"(a[mt][2]), "r"(a[mt][3]),
                          "r"(b[nt][0]), "r"(b[nt][1]));
                }
        }
    };

    ldgA(0);
    cpB(0, 0);
    asm volatile("cp.async.commit_group;\n");

    for (int it = 0; it < KTILES; ++it) {
        const int buf = it & 1;
        stsA(buf);                       // stage `it` A data into smem
        if (it + 1 < KTILES) {
            ldgA(it + 1);                // overlap next A fetch with compute
            cpB(it + 1, buf ^ 1);
            asm volatile("cp.async.commit_group;\n");
            asm volatile("cp.async.wait_group 1;\n");
        } else {
            asm volatile("cp.async.wait_group 0;\n");
        }
        __syncthreads();
        compute(buf);
        __syncthreads();
    }

    // Epilogue: fragment -> g_support (fp32, row-major)
    float* Cp = g_support + (size_t)m0 * FDIM;
    #pragma unroll
    for (int mt = 0; mt < 2; ++mt) {
        int r0 = wm * 32 + mt * 16 + (lane >> 2);
        #pragma unroll
        for (int nt = 0; nt < 8; ++nt) {
            int c0 = wn * 64 + nt * 8 + (lane & 3) * 2;
            *(float2*)(Cp + (size_t)r0 * FDIM + c0)       = make_float2(acc[mt][nt][0], acc[mt][nt][1]);
            *(float2*)(Cp + (size_t)(r0 + 8) * FDIM + c0) = make_float2(acc[mt][nt][2], acc[mt][nt][3]);
        }
    }
}

// ---------------------------------------------------------------------------
// h = relu( [X | g_support] @ W + b ), W is [256,128].
// Writes fp32 to `out`; optionally also bf16 to g_featb (input to next SpMM).
// Block: 64 rows x 128 cols, 256 threads, thread tile 8x4.
// ---------------------------------------------------------------------------
__global__ void __launch_bounds__(256)
sage_linear_kernel(const float* __restrict__ X,
                   const float* __restrict__ W,
                   const float* __restrict__ bias,
                   float* __restrict__ out,
                   int write_bf16) {
    __shared__ float INs[64][16];
    __shared__ float Ws[16][128];
    const int t  = threadIdx.x;
    const int tr = t >> 5;     // 0..7  (warp id == row group)
    const int tc = t & 31;     // 0..31 (col group of 4)
    const int row0 = blockIdx.x * 64;

    float acc[8][4];
    #pragma unroll
    for (int i = 0; i < 8; ++i)
        #pragma unroll
        for (int j = 0; j < 4; ++j) acc[i][j] = 0.f;

    for (int kb = 0; kb < 16; ++kb) {
        const int kbase = kb * 16;
        #pragma unroll
        for (int j = 0; j < 4; ++j) {
            int idx = t + j * 256;
            int r = idx >> 4, kk = idx & 15;
            int k = kbase + kk;
            float v;
            if (k < FDIM) v = X[(size_t)(row0 + r) * FDIM + k];
            else          v = g_support[(size_t)(row0 + r) * FDIM + (k - FDIM)];
            INs[r][kk] = v;
        }
        #pragma unroll
        for (int j = 0; j < 8; ++j) {
            int idx = t + j * 256;
            int wr = idx >> 7, wc = idx & 127;
            Ws[wr][wc] = W[(size_t)(kbase + wr) * FDIM + wc];
        }
        __syncthreads();
        #pragma unroll
        for (int kk = 0; kk < 16; ++kk) {
            float4 w = *(const float4*)&Ws[kk][tc * 4];
            #pragma unroll
            for (int i = 0; i < 8; ++i) {
                float xv = INs[tr * 8 + i][kk];
                acc[i][0] = fmaf(xv, w.x, acc[i][0]);
                acc[i][1] = fmaf(xv, w.y, acc[i][1]);
                acc[i][2] = fmaf(xv, w.z, acc[i][2]);
                acc[i][3] = fmaf(xv, w.w, acc[i][3]);
            }
        }
        __syncthreads();
    }

    const float4 bv = *(const float4*)&bias[tc * 4];
    #pragma unroll
    for (int i = 0; i < 8; ++i) {
        int r = row0 + tr * 8 + i;
        float4 o;
        o.x = fmaxf(acc[i][0] + bv.x, 0.f);
        o.y = fmaxf(acc[i][1] + bv.y, 0.f);
        o.z = fmaxf(acc[i][2] + bv.z, 0.f);
        o.w = fmaxf(acc[i][3] + bv.w, 0.f);
        *(float4*)&out[(size_t)r * FDIM + tc * 4] = o;
        if (write_bf16) {
            __nv_bfloat162 lo = __float22bfloat162_rn(make_float2(o.x, o.y));
            __nv_bfloat162 hi = __float22bfloat162_rn(make_float2(o.z, o.w));
            uint2 v;
            v.x = *(uint32_t*)&lo;
            v.y = *(uint32_t*)&hi;
            *(uint2*)&g_featb[(size_t)r * FDIM + tc * 4] = v;
        }
    }
}

// ---------------------------------------------------------------------------
// logits = h2 @ Wl + bl ; log_probs = logits - logsumexp(logits)
// 128 threads/block, one row per thread; h2 tile + Wl staged in smem.
// ---------------------------------------------------------------------------
__global__ void __launch_bounds__(128)
classifier_kernel(const float* __restrict__ H,
                  const float* __restrict__ Wl,
                  const float* __restrict__ bl,
                  float* __restrict__ logp,
                  float* __restrict__ logits) {
    extern __shared__ float sh[];
    float* Hs  = sh;                  // 128*129 (padded rows: conflict-free)
    float* Wls = sh + 128 * 129;      // 128*40
    float* bls = Wls + 128 * NCLS;    // 40
    const int t = threadIdx.x;
    const int row0 = blockIdx.x * 128;

    for (int j = 0; j < 128; ++j)
        Hs[j * 129 + t] = H[(size_t)(row0 + j) * FDIM + t];
    for (int idx = t; idx < 128 * NCLS; idx += 128)
        Wls[idx] = Wl[idx];
    if (t < NCLS) bls[t] = bl[t];
    __syncthreads();

    float acc[NCLS];
    #pragma unroll
    for (int c = 0; c < NCLS; ++c) acc[c] = bls[c];

    const float* hr = &Hs[t * 129];
    #pragma unroll 4
    for (int k = 0; k < FDIM; ++k) {
        float xv = hr[k];
        #pragma unroll
        for (int c = 0; c < NCLS; c += 4) {
            float4 w = *(const float4*)&Wls[k * NCLS + c];
            acc[c + 0] = fmaf(xv, w.x, acc[c + 0]);
            acc[c + 1] = fmaf(xv, w.y, acc[c + 1]);
            acc[c + 2] = fmaf(xv, w.z, acc[c + 2]);
            acc[c + 3] = fmaf(xv, w.w, acc[c + 3]);
        }
    }

    float m = acc[0];
    #pragma unroll
    for (int c = 1; c < NCLS; ++c) m = fmaxf(m, acc[c]);
    float s = 0.f;
    #pragma unroll
    for (int c = 0; c < NCLS; ++c) s += __expf(acc[c] - m);
    float lse = m + __logf(s);

    size_t ro = (size_t)(row0 + t) * NCLS;
    #pragma unroll
    for (int c = 0; c < NCLS; ++c) {
        logits[ro + c] = acc[c];
        logp[ro + c]   = acc[c] - lse;
    }
}

// ---------------------------------------------------------------------------
extern "C" void kernel_launch(void* const* d_in, const int* in_sizes, int n_in,
                              void* d_out, int out_size) {
    (void)in_sizes; (void)n_in; (void)out_size;
    const float* x   = (const float*)d_in[0];
    const float* adj = (const float*)d_in[1];
    const float* W1  = (const float*)d_in[2];
    const float* b1  = (const float*)d_in[3];
    const float* W2  = (const float*)d_in[4];
    const float* b2  = (const float*)d_in[5];
    const float* Wl  = (const float*)d_in[6];
    const float* bl  = (const float*)d_in[7];

    float* out    = (float*)d_out;
    float* logp   = out;                                  // [N, 40]
    float* h1     = logp + (size_t)N_NODES * NCLS;        // [N, 128]
    float* h2     = h1 + (size_t)N_NODES * FDIM;          // [N, 128]
    float* logits = h2 + (size_t)N_NODES * FDIM;          // [N, 40]

    const int cls_smem = (128 * 129 + 128 * NCLS + NCLS) * (int)sizeof(float);
    cudaFuncSetAttribute(spmm_kernel, cudaFuncAttributeMaxDynamicSharedMemorySize, 65536);
    cudaFuncSetAttribute(classifier_kernel, cudaFuncAttributeMaxDynamicSharedMemorySize, cls_smem);

    // 1) x -> bf16
    cvt_x_kernel<<<512, 256>>>(x);
    // 2) support = adj @ x
    spmm_kernel<<<N_NODES / BM, 256, 65536>>>(adj);
    // 3) h1 = relu([x|s]@W1 + b1)  (also emits bf16 h1 into g_featb)
    sage_linear_kernel<<<N_NODES / 64, 256>>>(x, W1, b1, h1, 1);
    // 4) support = adj @ h1
    spmm_kernel<<<N_NODES / BM, 256, 65536>>>(adj);
    // 5) h2 = relu([h1|s]@W2 + b2)
    sage_linear_kernel<<<N_NODES / 64, 256>>>(h1, W2, b2, h2, 0);
    // 6) logits + log_softmax
    classifier_kernel<<<N_NODES / 128, 128, cls_smem>>>(h2, Wl, bl, logp, logits);
}